// round 16
// baseline (speedup 1.0000x reference)
#include <cuda_runtime.h>

#define NQ      22
#define NSTATE  (1u << NQ)
#define NLAYERS 8

typedef unsigned long long u64;

// Ping-pong statevector buffers (64 MB total)
__device__ __align__(16) float2 g_state[2][NSTATE];
// Fused single-qubit unitaries U = RX*RZ*RY (float2, for layer-0 tables)
__device__ float2 g_U[NLAYERS][NQ][4];
// ZYZ real-rotation coefficients per gate: [0]=dup(c) [1]=dup(s) [2]=dup(-s)
__device__ u64 g_Rpk[NLAYERS][NQ][3];
// Broadcast copy in constant memory (filled by D2D memcpy after prep_gates)
__constant__ u64 c_Rpk[NLAYERS][NQ][3];
// ZYZ half-angles
__device__ float g_pA[NLAYERS][NQ];
__device__ float g_pB[NLAYERS][NQ];
// Combined inter-layer diagonal tables, applied at L-load of layer L:
//   W_L[t] = B_L[t] * A_{L-1}[gray(t)]      (A term absent for L=1)
__device__ float2 g_Whi[NLAYERS][2048];
__device__ __align__(16) float2 g_Wlo[NLAYERS][2][2048];
// Product-state tables for layer 0
__device__ float2 g_Phi[2048];
__device__ float2 g_Plo[2048];

// ---------------------------------------------------------------------------
// f32x2 packed helpers
// ---------------------------------------------------------------------------
__device__ __forceinline__ u64 pk2(float lo, float hi) {
    u64 r; asm("mov.b64 %0, {%1, %2};" : "=l"(r) : "f"(lo), "f"(hi)); return r;
}
__device__ __forceinline__ void unpk2(u64 v, float& lo, float& hi) {
    asm("mov.b64 {%0, %1}, %2;" : "=f"(lo), "=f"(hi) : "l"(v));
}
__device__ __forceinline__ u64 f2mul(u64 a, u64 b) {
    u64 r; asm("mul.rn.f32x2 %0, %1, %2;" : "=l"(r) : "l"(a), "l"(b)); return r;
}
__device__ __forceinline__ u64 f2fma(u64 a, u64 b, u64 c) {
    u64 r; asm("fma.rn.f32x2 %0, %1, %2, %3;" : "=l"(r) : "l"(a), "l"(b), "l"(c)); return r;
}
__device__ __forceinline__ float2 cmulf(float2 a, float2 b) {
    return make_float2(a.x * b.x - a.y * b.y, a.x * b.y + a.y * b.x);
}
__device__ __forceinline__ u64 apply_phase(float2 w, u64 x) {
    float re, im; unpk2(x, re, im);
    return pk2(w.x * re - w.y * im, w.x * im + w.y * re);
}

// Real Givens butterfly: y0 = c*x0 - s*x1 ; y1 = s*x0 + c*x1  (4 f32x2 ops)
__device__ __forceinline__ void rbfly(u64 c, u64 s, u64 ns, u64& x0, u64& x1) {
    u64 y0 = f2fma(c, x0, f2mul(ns, x1));
    u64 y1 = f2fma(c, x1, f2mul(s, x0));
    x0 = y0; x1 = y1;
}

// Apply gate (layer, q) across register bit K; coefs from constant memory.
template<int K>
__device__ __forceinline__ void gate_q(int layer, int q, u64 a[16]) {
    u64 c = c_Rpk[layer][q][0], s = c_Rpk[layer][q][1], ns = c_Rpk[layer][q][2];
#pragma unroll
    for (int m = 0; m < 8; m++) {
        int j0 = ((m >> K) << (K + 1)) | (m & ((1 << K) - 1));
        rbfly(c, s, ns, a[j0], a[j0 | (1 << K)]);
    }
}

// Swizzles — bank-walked <=2-way for every phase pattern in each kernel
__device__ __forceinline__ int SWL2(int i) {
    return i ^ ((i >> 5) & 3) ^ ((i >> 2) & 4) ^ ((i >> 4) & 8);
}
__device__ __forceinline__ int SWH2(int i) {
    return i ^ ((i >> 5) & 3) ^ ((i >> 4) & 8);
}

// ---------------------------------------------------------------------------
// Prep stage 1 (1 block): fused U matrices + ZYZ decomposition per gate.
// ---------------------------------------------------------------------------
__global__ void prep_gates(const float* __restrict__ p) {
    int tid = threadIdx.x;
    if (tid >= NLAYERS * NQ) return;
    int l = tid / NQ, q = tid % NQ;
    float ty = p[l * 3 * NQ + q];
    float tz = p[l * 3 * NQ + NQ + q];
    float tx = p[l * 3 * NQ + 2 * NQ + q];
    float cy = cosf(0.5f * ty), sy = sinf(0.5f * ty);
    float cz = cosf(0.5f * tz), sz = sinf(0.5f * tz);
    float cx = cosf(0.5f * tx), sx = sinf(0.5f * tx);
    float2 em = make_float2(cz, -sz);
    float2 ep = make_float2(cz, sz);
    float2 u00 = make_float2(cx * cy * em.x + sx * sy * ep.y,
                             cx * cy * em.y - sx * sy * ep.x);
    float2 u01 = make_float2(-cx * sy * em.x + sx * cy * ep.y,
                             -cx * sy * em.y - sx * cy * ep.x);
    float2 u10 = make_float2(sx * cy * em.y + cx * sy * ep.x,
                             -sx * cy * em.x + cx * sy * ep.y);
    float2 u11 = make_float2(-sx * sy * em.y + cx * cy * ep.x,
                             sx * sy * em.x + cx * cy * ep.y);
    g_U[l][q][0] = u00; g_U[l][q][1] = u01;
    g_U[l][q][2] = u10; g_U[l][q][3] = u11;
    float c = sqrtf(u00.x * u00.x + u00.y * u00.y);
    float s = sqrtf(u01.x * u01.x + u01.y * u01.y);
    float p00 = atan2f(u00.y, u00.x);
    float p01 = atan2f(u01.y, u01.x);
    const float PI = 3.14159265358979f;
    float pA = 0.5f * (-p00 - p01 + PI);
    float pB = 0.5f * (-p00 + p01 - PI);
    g_pA[l][q] = pA; g_pB[l][q] = pB;
    g_Rpk[l][q][0] = pk2(c, c);
    g_Rpk[l][q][1] = pk2(s, s);
    g_Rpk[l][q][2] = pk2(-s, -s);
}

// ---------------------------------------------------------------------------
// Prep stage 2 (grid-parallel): product tables + combined diag tables.
// ---------------------------------------------------------------------------
__global__ void prep_tables() {
    int idx = blockIdx.x * blockDim.x + threadIdx.x;
    if (idx < 2048) {
        int i = idx;
        float2 ph = make_float2(1.f, 0.f);
        float2 pl = make_float2(1.f, 0.f);
        for (int q = 0; q <= 10; q++) {
            int b = (i >> (10 - q)) & 1;
            ph = cmulf(ph, g_U[0][q][b * 2]);
        }
        for (int q = 11; q <= 21; q++) {
            int b = (i >> (21 - q)) & 1;
            pl = cmulf(pl, g_U[0][q][b * 2]);
        }
        g_Phi[i] = ph;
        g_Plo[i] = pl;
    } else if (idx < 2048 + 7 * 2048) {
        int k0 = idx - 2048;
        int L = 1 + (k0 >> 11), x = k0 & 2047;
        float ang = 0.f;
        for (int k = 0; k < 11; k++) {
            int xb = (x >> k) & 1;
            ang += (xb ? 1.f : -1.f) * g_pB[L][10 - k];
            if (L >= 2) {
                int gb = xb ^ ((k < 10) ? ((x >> (k + 1)) & 1) : 0);
                ang += (gb ? 1.f : -1.f) * g_pA[L - 1][10 - k];
            }
        }
        float sv, cv; sincosf(ang, &sv, &cv);
        g_Whi[L][x] = make_float2(cv, sv);
    } else if (idx < 2048 + 7 * 2048 + 7 * 2 * 2048) {
        int k0 = idx - (2048 + 7 * 2048);
        int L = 1 + (k0 >> 12), carry = (k0 >> 11) & 1, x = k0 & 2047;
        float ang = 0.f;
        for (int b = 0; b < 11; b++) {
            int xb = (x >> b) & 1;
            ang += (xb ? 1.f : -1.f) * g_pB[L][21 - b];
            if (L >= 2) {
                int gb = xb ^ ((b < 10) ? ((x >> (b + 1)) & 1) : carry);
                ang += (gb ? 1.f : -1.f) * g_pA[L - 1][21 - b];
            }
        }
        float sv, cv; sincosf(ang, &sv, &cv);
        g_Wlo[L][carry][x] = make_float2(cv, sv);
    }
}

#define SMEM_BYTES (8192 * 8)
#define GRID_HALF  256   // 256 resident blocks (<=296 slots), 2 tiles each

// ---------------------------------------------------------------------------
// L kernel: two 8192-amp tiles per block (h = bid, bid+256) — single balanced
// wave, no quantization tail. Per tile: 12 real rotations on bits 0..11
// (qubits 10..21), 3 phases, 2 transposes. Load folds CNOT gray + W diag.
// ---------------------------------------------------------------------------
__global__ void __launch_bounds__(512, 2) kernelL(int layer, int srcIdx, int dstIdx, int first) {
    extern __shared__ u64 sh[];
    const int t = threadIdx.x;                 // 9 bits
    const int tm = t & 255, b12 = t >> 8;
    u64 a[16];

    for (int w = 0; w < 2; w++) {
        const unsigned h = blockIdx.x + (w << 8);   // global bits 13..21
        const unsigned ghi = h ^ (h >> 1);
        const unsigned c12 = (h & 1u) << 12;

        // ---- Phase A: i = (b12<<12)|(rr<<9)|(tm<<1)|v ; a idx = (rr<<1)|v
        if (first) {
#pragma unroll
            for (int r = 0; r < 16; r++) {
                unsigned i = (b12 << 12) | ((r >> 1) << 9) | (tm << 1) | (r & 1);
                unsigned glo = (i ^ (i >> 1)) ^ c12;
                float2 ph = g_Phi[(ghi << 2) | (glo >> 11)];
                float2 pl = g_Plo[glo & 2047];
                float2 v = cmulf(ph, pl);
                a[r] = pk2(v.x, v.y);
            }
        } else {
            const float2* __restrict__ src = g_state[srcIdx] + ((size_t)ghi << 13);
#pragma unroll
            for (int rr = 0; rr < 8; rr++) {
                unsigned i = (b12 << 12) | (rr << 9) | (tm << 1);
                unsigned glo = (i ^ (i >> 1)) ^ c12;
                unsigned base = glo & ~1u;
                ulonglong2 q = __ldg(reinterpret_cast<const ulonglong2*>(src + base));
                if (glo & 1) { a[(rr << 1)] = q.y; a[(rr << 1) | 1] = q.x; }
                else         { a[(rr << 1)] = q.x; a[(rr << 1) | 1] = q.y; }
            }
        }
        // Combined diag W at logical t = (h<<13)|i (pair-vectorized Wlo loads)
        {
            const float2 whi0 = __ldg(&g_Whi[layer][(h << 2) | (b12 << 1)]);
            const float2 whi1 = __ldg(&g_Whi[layer][(h << 2) | (b12 << 1) | 1]);
#pragma unroll
            for (int rr = 0; rr < 8; rr++) {
                int carry = rr >> 2;
                int ilo = ((rr & 3) << 9) | (tm << 1);
                float4 wv = __ldg(reinterpret_cast<const float4*>(&g_Wlo[layer][carry][ilo]));
                float2 whi = carry ? whi1 : whi0;
                a[(rr << 1)]     = apply_phase(cmulf(whi, make_float2(wv.x, wv.y)), a[(rr << 1)]);
                a[(rr << 1) | 1] = apply_phase(cmulf(whi, make_float2(wv.z, wv.w)), a[(rr << 1) | 1]);
            }
        }
        gate_q<0>(layer, 21, a);
        gate_q<1>(layer, 12, a);
        gate_q<2>(layer, 11, a);
        gate_q<3>(layer, 10, a);
#pragma unroll
        for (int r = 0; r < 16; r++) {
            unsigned i = (b12 << 12) | ((r >> 1) << 9) | (tm << 1) | (r & 1);
            sh[SWL2(i)] = a[r];
        }
        __syncthreads();

        // ---- Phase B: reg bits local {1,2,3,8} -> q20,q19,q18,q13
        const int u0 = t & 1, umid = (t >> 1) & 15, uhi = t >> 5;
#pragma unroll
        for (int r = 0; r < 16; r++) {
            int i = u0 | ((r & 7) << 1) | (umid << 4) | ((r >> 3) << 8) | (uhi << 9);
            a[r] = sh[SWL2(i)];
        }
        gate_q<0>(layer, 20, a);
        gate_q<1>(layer, 19, a);
        gate_q<2>(layer, 18, a);
        gate_q<3>(layer, 13, a);
#pragma unroll
        for (int r = 0; r < 16; r++) {
            int i = u0 | ((r & 7) << 1) | (umid << 4) | ((r >> 3) << 8) | (uhi << 9);
            sh[SWL2(i)] = a[r];
        }
        __syncthreads();

        // ---- Phase C: i = (hi5<<8)|(r<<4)|lo4 ; reg bits local 4..7 -> q17..q14
        const int hi5 = t >> 4, lo4 = t & 15;
#pragma unroll
        for (int r = 0; r < 16; r++) a[r] = sh[SWL2((hi5 << 8) | (r << 4) | lo4)];
        gate_q<0>(layer, 17, a);
        gate_q<1>(layer, 16, a);
        gate_q<2>(layer, 15, a);
        gate_q<3>(layer, 14, a);

        float2* __restrict__ dst = g_state[dstIdx] + ((size_t)h << 13);
#pragma unroll
        for (int r = 0; r < 16; r++) {
            float re, im; unpk2(a[r], re, im);
            dst[(hi5 << 8) | (r << 4) | lo4] = make_float2(re, im);
        }
        if (w == 0) __syncthreads();           // smem reuse hazard between tiles
    }
}

// ---------------------------------------------------------------------------
// H kernel: two tiles per block (f = bid, bid+256). Per tile: bits {0..2} U
// {12..21}, 10 real rotations on bits 12..21 (qubits 0..9).
// j(i) = ((i>>3)<<12)|(f<<3)|(i&7). Phases: A{3,2,1}  B{7,6,5,4}  C{9,8,0}.
// ---------------------------------------------------------------------------
__global__ void __launch_bounds__(512, 2) kernelH(int layer, int srcIdx, int dstIdx,
                                                  float* __restrict__ probs) {
    extern __shared__ u64 sh[];
    const int t = threadIdx.x;                 // 9 bits
    const int s8 = t >> 8, shi = (t >> 2) & 63, s10 = t & 3;
    u64 a[16];

    for (int w = 0; w < 2; w++) {
        const unsigned f = blockIdx.x + (w << 8);   // global bits 3..11

        // ---- Phase A: i = (s8<<12)|(rr<<9)|(shi<<3)|(s10<<1)|v
        {
            const float2* __restrict__ src = g_state[srcIdx];
            const unsigned jbase = ((((unsigned)s8 << 9) | shi) << 12) | (f << 3) | (s10 << 1);
#pragma unroll
            for (int rr = 0; rr < 8; rr++) {
                ulonglong2 q = __ldg(reinterpret_cast<const ulonglong2*>(src + (jbase | (rr << 18))));
                a[(rr << 1)] = q.x; a[(rr << 1) | 1] = q.y;
            }
        }
        gate_q<1>(layer, 3, a);    // local 9  -> qubit 3
        gate_q<2>(layer, 2, a);    // local 10 -> qubit 2
        gate_q<3>(layer, 1, a);    // local 11 -> qubit 1
#pragma unroll
        for (int r = 0; r < 16; r++) {
            int i = (s8 << 12) | ((r >> 1) << 9) | (shi << 3) | (s10 << 1) | (r & 1);
            sh[SWH2(i)] = a[r];
        }
        __syncthreads();

        // ---- Phase B: i = (hi4<<9)|(r<<5)|lo5 ; local 5..8 -> q7,q6,q5,q4
        const int hi4 = t >> 5, lo5 = t & 31;
#pragma unroll
        for (int r = 0; r < 16; r++) a[r] = sh[SWH2((hi4 << 9) | (r << 5) | lo5)];
        gate_q<0>(layer, 7, a);
        gate_q<1>(layer, 6, a);
        gate_q<2>(layer, 5, a);
        gate_q<3>(layer, 4, a);
#pragma unroll
        for (int r = 0; r < 16; r++) sh[SWH2((hi4 << 9) | (r << 5) | lo5)] = a[r];
        __syncthreads();

        // ---- Phase C: reg bits {0(v), 3(rB->q9), 4(rC->q8), 12(rD->q0)}
        const int wl = t & 3, wh = (t >> 2) & 127;
#pragma unroll
        for (int r = 0; r < 16; r++) {
            int i = ((r >> 3) << 12) | (wh << 5) | (((r >> 2) & 1) << 4)
                  | (((r >> 1) & 1) << 3) | (wl << 1) | (r & 1);
            a[r] = sh[SWH2(i)];
        }
        gate_q<1>(layer, 9, a);
        gate_q<2>(layer, 8, a);
        gate_q<3>(layer, 0, a);

        if (probs) {
            // layer 7: post-diag dropped (phase-invariant); fold final CNOT chain.
#pragma unroll
            for (int rp = 0; rp < 8; rp++) {
                int i_even = ((rp >> 2) << 12) | (wh << 5) | (((rp >> 1) & 1) << 4)
                           | ((rp & 1) << 3) | (wl << 1);
                unsigned j = (((unsigned)i_even >> 3) << 12) | (f << 3) | (unsigned)(i_even & 7);
                unsigned o = j;
                o ^= o >> 1; o ^= o >> 2; o ^= o >> 4; o ^= o >> 8; o ^= o >> 16;
                float r0, i0, r1, i1;
                unpk2(a[(rp << 1)], r0, i0);
                unpk2(a[(rp << 1) | 1], r1, i1);
                float p0 = fmaf(r0, r0, i0 * i0);
                float p1 = fmaf(r1, r1, i1 * i1);
                unsigned po = o & 1;
                float2 pr = po ? make_float2(p1, p0) : make_float2(p0, p1);
                *reinterpret_cast<float2*>(&probs[o & ~1u]) = pr;
            }
        } else {
            float2* __restrict__ dst = g_state[dstIdx];
#pragma unroll
            for (int rp = 0; rp < 8; rp++) {
                int i_even = ((rp >> 2) << 12) | (wh << 5) | (((rp >> 1) & 1) << 4)
                           | ((rp & 1) << 3) | (wl << 1);
                unsigned j = (((unsigned)i_even >> 3) << 12) | (f << 3) | (unsigned)(i_even & 7);
                ulonglong2 q;
                q.x = a[(rp << 1)]; q.y = a[(rp << 1) | 1];
                *reinterpret_cast<ulonglong2*>(dst + j) = q;
            }
        }
        if (w == 0) __syncthreads();           // smem reuse hazard between tiles
    }
}

// ---------------------------------------------------------------------------
extern "C" void kernel_launch(void* const* d_in, const int* in_sizes, int n_in,
                              void* d_out, int out_size) {
    (void)in_sizes; (void)n_in; (void)out_size;
    const float* params = (const float*)d_in[0];
    float* out = (float*)d_out;

    cudaFuncSetAttribute(kernelL, cudaFuncAttributeMaxDynamicSharedMemorySize, SMEM_BYTES);
    cudaFuncSetAttribute(kernelH, cudaFuncAttributeMaxDynamicSharedMemorySize, SMEM_BYTES);

    prep_gates<<<1, 192>>>(params);
    // Broadcast gate coefficients into constant memory (D2D copy, graph-legal)
    void* cdst = nullptr; void* csrc = nullptr;
    cudaGetSymbolAddress(&cdst, c_Rpk);
    cudaGetSymbolAddress(&csrc, g_Rpk);
    cudaMemcpyAsync(cdst, csrc, NLAYERS * NQ * 3 * sizeof(u64),
                    cudaMemcpyDeviceToDevice);
    prep_tables<<<88, 512>>>();

    // Layer 0 folded into tables; layer-(l-1) CNOT chain folded into L's gray
    // load; layer-7 chain folded into the prob scatter; both diagonals of each
    // layer boundary folded into ONE combined phase multiply at L-load.
    kernelL<<<GRID_HALF, 512, SMEM_BYTES>>>(1, /*src*/1, /*dst*/0, /*first*/1);
    kernelH<<<GRID_HALF, 512, SMEM_BYTES>>>(1, 0, 1, nullptr);
    for (int ll = 2; ll <= 7; ll++) {
        kernelL<<<GRID_HALF, 512, SMEM_BYTES>>>(ll, 1, 0, 0);
        kernelH<<<GRID_HALF, 512, SMEM_BYTES>>>(ll, 0, 1, (ll == 7) ? out : nullptr);
    }
}

// round 17
// speedup vs baseline: 1.0904x; 1.0904x over previous
#include <cuda_runtime.h>

#define NQ      22
#define NSTATE  (1u << NQ)
#define NLAYERS 8

typedef unsigned long long u64;

// Ping-pong statevector buffers (64 MB total)
__device__ __align__(16) float2 g_state[2][NSTATE];
// Fused single-qubit unitaries U = RX*RZ*RY (float2, for layer-0 tables)
__device__ float2 g_U[NLAYERS][NQ][4];
// ZYZ real-rotation coefficients per gate: [0]=dup(c) [1]=dup(s) [2]=dup(-s)
__device__ u64 g_Rpk[NLAYERS][NQ][3];
// Broadcast copy in constant memory (filled by D2D memcpy after prep_gates)
__constant__ u64 c_Rpk[NLAYERS][NQ][3];
// ZYZ half-angles
__device__ float g_pA[NLAYERS][NQ];
__device__ float g_pB[NLAYERS][NQ];
// Combined inter-layer diagonal tables, applied at L-load of layer L:
//   W_L[t] = B_L[t] * A_{L-1}[gray(t)]      (A term absent for L=1)
__device__ float2 g_Whi[NLAYERS][2048];
__device__ __align__(16) float2 g_Wlo[NLAYERS][2][2048];
// Product-state tables for layer 0
__device__ float2 g_Phi[2048];
__device__ float2 g_Plo[2048];

// ---------------------------------------------------------------------------
// f32x2 packed helpers
// ---------------------------------------------------------------------------
__device__ __forceinline__ u64 pk2(float lo, float hi) {
    u64 r; asm("mov.b64 %0, {%1, %2};" : "=l"(r) : "f"(lo), "f"(hi)); return r;
}
__device__ __forceinline__ void unpk2(u64 v, float& lo, float& hi) {
    asm("mov.b64 {%0, %1}, %2;" : "=f"(lo), "=f"(hi) : "l"(v));
}
__device__ __forceinline__ u64 f2mul(u64 a, u64 b) {
    u64 r; asm("mul.rn.f32x2 %0, %1, %2;" : "=l"(r) : "l"(a), "l"(b)); return r;
}
__device__ __forceinline__ u64 f2fma(u64 a, u64 b, u64 c) {
    u64 r; asm("fma.rn.f32x2 %0, %1, %2, %3;" : "=l"(r) : "l"(a), "l"(b), "l"(c)); return r;
}
__device__ __forceinline__ float2 cmulf(float2 a, float2 b) {
    return make_float2(a.x * b.x - a.y * b.y, a.x * b.y + a.y * b.x);
}
__device__ __forceinline__ u64 apply_phase(float2 w, u64 x) {
    float re, im; unpk2(x, re, im);
    return pk2(w.x * re - w.y * im, w.x * im + w.y * re);
}

// Real Givens butterfly: y0 = c*x0 - s*x1 ; y1 = s*x0 + c*x1  (4 f32x2 ops)
__device__ __forceinline__ void rbfly(u64 c, u64 s, u64 ns, u64& x0, u64& x1) {
    u64 y0 = f2fma(c, x0, f2mul(ns, x1));
    u64 y1 = f2fma(c, x1, f2mul(s, x0));
    x0 = y0; x1 = y1;
}

// Apply gate (layer, q) across register bit K; coefs from constant memory.
template<int K>
__device__ __forceinline__ void gate_q(int layer, int q, u64 a[16]) {
    u64 c = c_Rpk[layer][q][0], s = c_Rpk[layer][q][1], ns = c_Rpk[layer][q][2];
#pragma unroll
    for (int m = 0; m < 8; m++) {
        int j0 = ((m >> K) << (K + 1)) | (m & ((1 << K) - 1));
        rbfly(c, s, ns, a[j0], a[j0 | (1 << K)]);
    }
}

// Swizzles — bank-walked <=2-way for every phase pattern in each kernel
__device__ __forceinline__ int SWL2(int i) {
    return i ^ ((i >> 5) & 3) ^ ((i >> 2) & 4) ^ ((i >> 4) & 8);
}
__device__ __forceinline__ int SWH2(int i) {
    return i ^ ((i >> 5) & 3) ^ ((i >> 4) & 8);
}

// ---------------------------------------------------------------------------
// Prep stage 1 (1 block): fused U matrices + ZYZ decomposition per gate.
// ---------------------------------------------------------------------------
__global__ void prep_gates(const float* __restrict__ p) {
    int tid = threadIdx.x;
    if (tid >= NLAYERS * NQ) return;
    int l = tid / NQ, q = tid % NQ;
    float ty = p[l * 3 * NQ + q];
    float tz = p[l * 3 * NQ + NQ + q];
    float tx = p[l * 3 * NQ + 2 * NQ + q];
    float cy = cosf(0.5f * ty), sy = sinf(0.5f * ty);
    float cz = cosf(0.5f * tz), sz = sinf(0.5f * tz);
    float cx = cosf(0.5f * tx), sx = sinf(0.5f * tx);
    float2 em = make_float2(cz, -sz);
    float2 ep = make_float2(cz, sz);
    float2 u00 = make_float2(cx * cy * em.x + sx * sy * ep.y,
                             cx * cy * em.y - sx * sy * ep.x);
    float2 u01 = make_float2(-cx * sy * em.x + sx * cy * ep.y,
                             -cx * sy * em.y - sx * cy * ep.x);
    float2 u10 = make_float2(sx * cy * em.y + cx * sy * ep.x,
                             -sx * cy * em.x + cx * sy * ep.y);
    float2 u11 = make_float2(-sx * sy * em.y + cx * cy * ep.x,
                             sx * sy * em.x + cx * cy * ep.y);
    g_U[l][q][0] = u00; g_U[l][q][1] = u01;
    g_U[l][q][2] = u10; g_U[l][q][3] = u11;
    float c = sqrtf(u00.x * u00.x + u00.y * u00.y);
    float s = sqrtf(u01.x * u01.x + u01.y * u01.y);
    float p00 = atan2f(u00.y, u00.x);
    float p01 = atan2f(u01.y, u01.x);
    const float PI = 3.14159265358979f;
    float pA = 0.5f * (-p00 - p01 + PI);
    float pB = 0.5f * (-p00 + p01 - PI);
    g_pA[l][q] = pA; g_pB[l][q] = pB;
    g_Rpk[l][q][0] = pk2(c, c);
    g_Rpk[l][q][1] = pk2(s, s);
    g_Rpk[l][q][2] = pk2(-s, -s);
}

// ---------------------------------------------------------------------------
// Prep stage 2 (grid-parallel): product tables + combined diag tables.
// ---------------------------------------------------------------------------
__global__ void prep_tables() {
    int idx = blockIdx.x * blockDim.x + threadIdx.x;
    if (idx < 2048) {
        int i = idx;
        float2 ph = make_float2(1.f, 0.f);
        float2 pl = make_float2(1.f, 0.f);
        for (int q = 0; q <= 10; q++) {
            int b = (i >> (10 - q)) & 1;
            ph = cmulf(ph, g_U[0][q][b * 2]);
        }
        for (int q = 11; q <= 21; q++) {
            int b = (i >> (21 - q)) & 1;
            pl = cmulf(pl, g_U[0][q][b * 2]);
        }
        g_Phi[i] = ph;
        g_Plo[i] = pl;
    } else if (idx < 2048 + 7 * 2048) {
        int k0 = idx - 2048;
        int L = 1 + (k0 >> 11), x = k0 & 2047;
        float ang = 0.f;
        for (int k = 0; k < 11; k++) {
            int xb = (x >> k) & 1;
            ang += (xb ? 1.f : -1.f) * g_pB[L][10 - k];
            if (L >= 2) {
                int gb = xb ^ ((k < 10) ? ((x >> (k + 1)) & 1) : 0);
                ang += (gb ? 1.f : -1.f) * g_pA[L - 1][10 - k];
            }
        }
        float sv, cv; sincosf(ang, &sv, &cv);
        g_Whi[L][x] = make_float2(cv, sv);
    } else if (idx < 2048 + 7 * 2048 + 7 * 2 * 2048) {
        int k0 = idx - (2048 + 7 * 2048);
        int L = 1 + (k0 >> 12), carry = (k0 >> 11) & 1, x = k0 & 2047;
        float ang = 0.f;
        for (int b = 0; b < 11; b++) {
            int xb = (x >> b) & 1;
            ang += (xb ? 1.f : -1.f) * g_pB[L][21 - b];
            if (L >= 2) {
                int gb = xb ^ ((b < 10) ? ((x >> (b + 1)) & 1) : carry);
                ang += (gb ? 1.f : -1.f) * g_pA[L - 1][21 - b];
            }
        }
        float sv, cv; sincosf(ang, &sv, &cv);
        g_Wlo[L][carry][x] = make_float2(cv, sv);
    }
}

#define SMEM_BYTES (8192 * 8)

// ---------------------------------------------------------------------------
// L kernel: tile = 8192 contiguous amps (bits 0..12), 12 real rotations on
// bits 0..11 (qubits 10..21). blockIdx = global bits 13..21 (grid 512).
// Gray pairs stay aligned pairs -> LDG.128 state loads.
// Phases: A{21,12,11,10}  B{20,19,18,13}  C{17,16,15,14}.
// PDL: wait before first dependent load; trigger before epilogue stores.
// ---------------------------------------------------------------------------
__global__ void __launch_bounds__(512, 2) kernelL(int layer, int srcIdx, int dstIdx, int first) {
    extern __shared__ u64 sh[];
    const int t = threadIdx.x;                 // 9 bits
    const unsigned h = blockIdx.x;             // global bits 13..21 (9 bits)
    const unsigned ghi = h ^ (h >> 1);
    const unsigned c12 = (h & 1u) << 12;
    u64 a[16];

    const int tm = t & 255, b12 = t >> 8;

    cudaGridDependencySynchronize();           // predecessor's stores visible

    // ---- Phase A: i = (b12<<12)|(rr<<9)|(tm<<1)|v ; a idx = (rr<<1)|v
    if (first) {
#pragma unroll
        for (int r = 0; r < 16; r++) {
            unsigned i = (b12 << 12) | ((r >> 1) << 9) | (tm << 1) | (r & 1);
            unsigned glo = (i ^ (i >> 1)) ^ c12;
            float2 ph = g_Phi[(ghi << 2) | (glo >> 11)];
            float2 pl = g_Plo[glo & 2047];
            float2 v = cmulf(ph, pl);
            a[r] = pk2(v.x, v.y);
        }
    } else {
        const float2* __restrict__ src = g_state[srcIdx] + ((size_t)ghi << 13);
        const bool sw = (tm & 1) != 0;         // glo&1 == bit1(i) == tm&1, uniform
#pragma unroll
        for (int rr = 0; rr < 8; rr++) {
            unsigned i = (b12 << 12) | (rr << 9) | (tm << 1);
            unsigned glo = (i ^ (i >> 1)) ^ c12;
            unsigned base = glo & ~1u;
            ulonglong2 q = __ldg(reinterpret_cast<const ulonglong2*>(src + base));
            if (sw) { a[(rr << 1)] = q.y; a[(rr << 1) | 1] = q.x; }
            else    { a[(rr << 1)] = q.x; a[(rr << 1) | 1] = q.y; }
        }
    }
    // Combined diag W at logical t = (h<<13)|i (pair-vectorized Wlo loads)
    {
        const float2 whi0 = __ldg(&g_Whi[layer][(h << 2) | (b12 << 1)]);
        const float2 whi1 = __ldg(&g_Whi[layer][(h << 2) | (b12 << 1) | 1]);
#pragma unroll
        for (int rr = 0; rr < 8; rr++) {
            int carry = rr >> 2;
            int ilo = ((rr & 3) << 9) | (tm << 1);
            float4 wv = __ldg(reinterpret_cast<const float4*>(&g_Wlo[layer][carry][ilo]));
            float2 whi = carry ? whi1 : whi0;
            a[(rr << 1)]     = apply_phase(cmulf(whi, make_float2(wv.x, wv.y)), a[(rr << 1)]);
            a[(rr << 1) | 1] = apply_phase(cmulf(whi, make_float2(wv.z, wv.w)), a[(rr << 1) | 1]);
        }
    }
    gate_q<0>(layer, 21, a);
    gate_q<1>(layer, 12, a);
    gate_q<2>(layer, 11, a);
    gate_q<3>(layer, 10, a);
#pragma unroll
    for (int r = 0; r < 16; r++) {
        unsigned i = (b12 << 12) | ((r >> 1) << 9) | (tm << 1) | (r & 1);
        sh[SWL2(i)] = a[r];
    }
    __syncthreads();

    // ---- Phase B: reg bits local {1,2,3,8} -> q20,q19,q18,q13
    const int u0 = t & 1, umid = (t >> 1) & 15, uhi = t >> 5;
#pragma unroll
    for (int r = 0; r < 16; r++) {
        int i = u0 | ((r & 7) << 1) | (umid << 4) | ((r >> 3) << 8) | (uhi << 9);
        a[r] = sh[SWL2(i)];
    }
    gate_q<0>(layer, 20, a);
    gate_q<1>(layer, 19, a);
    gate_q<2>(layer, 18, a);
    gate_q<3>(layer, 13, a);
#pragma unroll
    for (int r = 0; r < 16; r++) {
        int i = u0 | ((r & 7) << 1) | (umid << 4) | ((r >> 3) << 8) | (uhi << 9);
        sh[SWL2(i)] = a[r];
    }
    __syncthreads();

    // ---- Phase C: i = (hi5<<8)|(r<<4)|lo4 ; reg bits local 4..7 -> q17..q14
    const int hi5 = t >> 4, lo4 = t & 15;
#pragma unroll
    for (int r = 0; r < 16; r++) a[r] = sh[SWL2((hi5 << 8) | (r << 4) | lo4)];
    gate_q<0>(layer, 17, a);
    gate_q<1>(layer, 16, a);
    gate_q<2>(layer, 15, a);
    gate_q<3>(layer, 14, a);

    cudaTriggerProgrammaticLaunchCompletion(); // successor may dispatch now

    float2* __restrict__ dst = g_state[dstIdx] + ((size_t)h << 13);
#pragma unroll
    for (int r = 0; r < 16; r++) {
        float re, im; unpk2(a[r], re, im);
        dst[(hi5 << 8) | (r << 4) | lo4] = make_float2(re, im);
    }
}

// ---------------------------------------------------------------------------
// H kernel: tile bits {0..2} U {12..21} (8192 amps), 10 real rotations on
// global bits 12..21 (qubits 0..9). blockIdx = global bits 3..11 (grid 512).
// j(i) = ((i>>3)<<12)|(f<<3)|(i&7). Phases: A{3,2,1}  B{7,6,5,4}  C{9,8,0}.
// PDL: wait before first dependent load; trigger before epilogue stores.
// ---------------------------------------------------------------------------
__global__ void __launch_bounds__(512, 2) kernelH(int layer, int srcIdx, int dstIdx,
                                                  float* __restrict__ probs) {
    extern __shared__ u64 sh[];
    const int t = threadIdx.x;                 // 9 bits
    const unsigned f = blockIdx.x;             // global bits 3..11 (9 bits)
    u64 a[16];

    const int s8 = t >> 8, shi = (t >> 2) & 63, s10 = t & 3;

    cudaGridDependencySynchronize();           // predecessor's stores visible

    // ---- Phase A: i = (s8<<12)|(rr<<9)|(shi<<3)|(s10<<1)|v ; a idx = (rr<<1)|v
    {
        const float2* __restrict__ src = g_state[srcIdx];
        const unsigned jbase = ((((unsigned)s8 << 9) | shi) << 12) | (f << 3) | (s10 << 1);
#pragma unroll
        for (int rr = 0; rr < 8; rr++) {
            ulonglong2 q = __ldg(reinterpret_cast<const ulonglong2*>(src + (jbase | (rr << 18))));
            a[(rr << 1)] = q.x; a[(rr << 1) | 1] = q.y;
        }
    }
    gate_q<1>(layer, 3, a);    // local 9  -> qubit 3
    gate_q<2>(layer, 2, a);    // local 10 -> qubit 2
    gate_q<3>(layer, 1, a);    // local 11 -> qubit 1
#pragma unroll
    for (int r = 0; r < 16; r++) {
        int i = (s8 << 12) | ((r >> 1) << 9) | (shi << 3) | (s10 << 1) | (r & 1);
        sh[SWH2(i)] = a[r];
    }
    __syncthreads();

    // ---- Phase B: i = (hi4<<9)|(r<<5)|lo5 ; local 5..8 -> q7,q6,q5,q4
    const int hi4 = t >> 5, lo5 = t & 31;
#pragma unroll
    for (int r = 0; r < 16; r++) a[r] = sh[SWH2((hi4 << 9) | (r << 5) | lo5)];
    gate_q<0>(layer, 7, a);
    gate_q<1>(layer, 6, a);
    gate_q<2>(layer, 5, a);
    gate_q<3>(layer, 4, a);
#pragma unroll
    for (int r = 0; r < 16; r++) sh[SWH2((hi4 << 9) | (r << 5) | lo5)] = a[r];
    __syncthreads();

    // ---- Phase C: reg bits {0(v), 3(rB->q9), 4(rC->q8), 12(rD->q0)}
    // i = (rD<<12)|(wh<<5)|(rC<<4)|(rB<<3)|(wl<<1)|v
    const int wl = t & 3, wh = (t >> 2) & 127;
#pragma unroll
    for (int r = 0; r < 16; r++) {
        int i = ((r >> 3) << 12) | (wh << 5) | (((r >> 2) & 1) << 4)
              | (((r >> 1) & 1) << 3) | (wl << 1) | (r & 1);
        a[r] = sh[SWH2(i)];
    }
    gate_q<1>(layer, 9, a);
    gate_q<2>(layer, 8, a);
    gate_q<3>(layer, 0, a);

    cudaTriggerProgrammaticLaunchCompletion(); // successor may dispatch now

    if (probs) {
        // layer 7: post-diag dropped (phase-invariant); fold final CNOT chain.
        // Pair (v=0/1) -> adjacent output slots {o&~1, o|1}.
#pragma unroll
        for (int rp = 0; rp < 8; rp++) {
            int i_even = ((rp >> 2) << 12) | (wh << 5) | (((rp >> 1) & 1) << 4)
                       | ((rp & 1) << 3) | (wl << 1);
            unsigned j = (((unsigned)i_even >> 3) << 12) | (f << 3) | (unsigned)(i_even & 7);
            unsigned o = j;
            o ^= o >> 1; o ^= o >> 2; o ^= o >> 4; o ^= o >> 8; o ^= o >> 16;
            float r0, i0, r1, i1;
            unpk2(a[(rp << 1)], r0, i0);
            unpk2(a[(rp << 1) | 1], r1, i1);
            float p0 = fmaf(r0, r0, i0 * i0);
            float p1 = fmaf(r1, r1, i1 * i1);
            unsigned po = o & 1;
            float2 pr = po ? make_float2(p1, p0) : make_float2(p0, p1);
            *reinterpret_cast<float2*>(&probs[o & ~1u]) = pr;
        }
    } else {
        float2* __restrict__ dst = g_state[dstIdx];
#pragma unroll
        for (int rp = 0; rp < 8; rp++) {
            int i_even = ((rp >> 2) << 12) | (wh << 5) | (((rp >> 1) & 1) << 4)
                       | ((rp & 1) << 3) | (wl << 1);
            unsigned j = (((unsigned)i_even >> 3) << 12) | (f << 3) | (unsigned)(i_even & 7);
            ulonglong2 q;
            q.x = a[(rp << 1)]; q.y = a[(rp << 1) | 1];
            *reinterpret_cast<ulonglong2*>(dst + j) = q;
        }
    }
}

// ---------------------------------------------------------------------------
// PDL launch helper: programmatic stream serialization on the capture stream.
// ---------------------------------------------------------------------------
template <typename... Args>
static void launch_pdl(void (*kern)(Args...), dim3 grid, dim3 block,
                       size_t smem, Args... args) {
    cudaLaunchConfig_t cfg = {};
    cfg.gridDim = grid;
    cfg.blockDim = block;
    cfg.dynamicSmemBytes = smem;
    cudaLaunchAttribute attr[1];
    attr[0].id = cudaLaunchAttributeProgrammaticStreamSerialization;
    attr[0].val.programmaticStreamSerializationAllowed = 1;
    cfg.attrs = attr;
    cfg.numAttrs = 1;
    cudaLaunchKernelEx(&cfg, kern, args...);
}

extern "C" void kernel_launch(void* const* d_in, const int* in_sizes, int n_in,
                              void* d_out, int out_size) {
    (void)in_sizes; (void)n_in; (void)out_size;
    const float* params = (const float*)d_in[0];
    float* out = (float*)d_out;

    cudaFuncSetAttribute(kernelL, cudaFuncAttributeMaxDynamicSharedMemorySize, SMEM_BYTES);
    cudaFuncSetAttribute(kernelH, cudaFuncAttributeMaxDynamicSharedMemorySize, SMEM_BYTES);

    prep_gates<<<1, 192>>>(params);
    // Broadcast gate coefficients into constant memory (D2D copy, graph-legal)
    void* cdst = nullptr; void* csrc = nullptr;
    cudaGetSymbolAddress(&cdst, c_Rpk);
    cudaGetSymbolAddress(&csrc, g_Rpk);
    cudaMemcpyAsync(cdst, csrc, NLAYERS * NQ * 3 * sizeof(u64),
                    cudaMemcpyDeviceToDevice);
    prep_tables<<<88, 512>>>();

    // Layer 0 folded into tables; layer-(l-1) CNOT chain folded into L's gray
    // load; layer-7 chain folded into the prob scatter; both diagonals of each
    // layer boundary folded into ONE combined phase multiply at L-load.
    // All heavy kernels chained with PDL to overlap dispatch/prologue.
    launch_pdl(kernelL, dim3(512), dim3(512), (size_t)SMEM_BYTES, 1, 1, 0, 1);
    launch_pdl(kernelH, dim3(512), dim3(512), (size_t)SMEM_BYTES, 1, 0, 1, (float*)nullptr);
    for (int ll = 2; ll <= 7; ll++) {
        launch_pdl(kernelL, dim3(512), dim3(512), (size_t)SMEM_BYTES, ll, 1, 0, 0);
        launch_pdl(kernelH, dim3(512), dim3(512), (size_t)SMEM_BYTES, ll, 0, 1,
                   (ll == 7) ? out : (float*)nullptr);
    }
}